// round 9
// baseline (speedup 1.0000x reference)
#include <cuda_runtime.h>
#include <cstdint>
#include <cub/cub.cuh>

// Fixed problem shape; all scratch static (device allocation forbidden).
static constexpr int NNODES = 40000;
static constexpr int SENT   = 1600000000;                 // 40000^2 < 2^31
static constexpr int BSHIFT = 15;                         // bucket = key >> 15
static constexpr int NB     = ((SENT - 1) >> BSHIFT) + 1; // 48829 buckets
static constexpr int STRIDE = 128;                        // slots/bucket (mean ~52)
static constexpr int SCT    = 1024;                       // scan threads
static constexpr int SCI    = 48;                         // items/thread: 49152 >= NB
static constexpr int NBP    = SCT * SCI;                  // padded count array size
static constexpr int BUCKET_BLOCKS = (NB + 7) / 8;        // 8 warps/block

__device__ int                g_cnt[NB];
__device__ int                g_ucnt[NBP];   // [NB, NBP) never written -> stays 0
__device__ int                g_uoff[NBP];
__device__ int                g_total;
__device__ unsigned long long g_pairs[(size_t)NB * STRIDE]; // (key<<32)|valbits
__device__ unsigned long long g_dedup[(size_t)NB * STRIDE]; // deduped pairs

// ---------------------------------------------------------------------------
__global__ void zero_cnt_kernel()
{
    int i = blockIdx.x * blockDim.x + threadIdx.x;
    if (i < NB) g_cnt[i] = 0;
}

// ---------------------------------------------------------------------------
// Scatter valid (key,val) pairs (both orientations) into fixed-stride buckets.
__global__ void scatter_kernel(const int* __restrict__ ei, const float* __restrict__ ea,
                               const float* __restrict__ t, int E)
{
    int e = blockIdx.x * blockDim.x + threadIdx.x;
    if (e >= E) return;
    float a = ea[e];
    if (a > t[0]) return;
    int r = ei[e];
    int c = ei[E + e];
    unsigned k1 = (unsigned)(r * NNODES + c);
    unsigned k2 = (unsigned)(c * NNODES + r);
    unsigned long long ab = (unsigned long long)__float_as_uint(a);
    int b1 = (int)(k1 >> BSHIFT);
    int p1 = atomicAdd(&g_cnt[b1], 1);
    if (p1 < STRIDE) g_pairs[(size_t)b1 * STRIDE + p1] = ((unsigned long long)k1 << 32) | ab;
    int b2 = (int)(k2 >> BSHIFT);
    int p2 = atomicAdd(&g_cnt[b2], 1);
    if (p2 < STRIDE) g_pairs[(size_t)b2 * STRIDE + p2] = ((unsigned long long)k2 << 32) | ab;
}

// ---------------------------------------------------------------------------
// Register-resident warp bitonic sort of P=32*R elements; element index
// i = lane + 32*r. In-lane stages (stride>=32) exchange registers; cross-lane
// stages use shfl_xor. Ascending; padding 0xFFFFFFFF sorts last.
template <int R>
__device__ __forceinline__ void bitonic_reg(unsigned v[R], int lane)
{
#pragma unroll
    for (int k = 2; k <= 32 * R; k <<= 1) {
#pragma unroll
        for (int j = k >> 1; j >= 32; j >>= 1) {
            int d = j >> 5;
#pragma unroll
            for (int r = 0; r < R; ++r) {
                if ((r & d) == 0) {
                    int i = lane + 32 * r;
                    bool up = ((i & k) == 0);
                    unsigned a = v[r], b = v[r + d];
                    if ((a > b) == up) { v[r] = b; v[r + d] = a; }
                }
            }
        }
#pragma unroll
        for (int j = ((k >> 1) > 16 ? 16 : (k >> 1)); j >= 1; j >>= 1) {
#pragma unroll
            for (int r = 0; r < R; ++r) {
                unsigned o = __shfl_xor_sync(0xFFFFFFFFu, v[r], j);
                int i = lane + 32 * r;
                bool keep_min = (((i & k) == 0) == ((lane & j) == 0));
                unsigned mn = v[r] < o ? v[r] : o;
                unsigned mx = v[r] < o ? o : v[r];
                v[r] = keep_min ? mn : mx;
            }
        }
    }
}

// One WARP per bucket (8 warps/block): register bitonic of (key15<<16|slot),
// spill once to smem, ballot dedupe with run sums, write deduped pairs + count.
__global__ void __launch_bounds__(256) sort_dedupe_kernel()
{
    __shared__ unsigned s_it[8][STRIDE];
    __shared__ float    s_val[8][STRIDE];
    int warp = threadIdx.x >> 5;
    int lane = threadIdx.x & 31;
    int b = blockIdx.x * 8 + warp;
    if (b >= NB) return;

    int m = g_cnt[b];
    if (m > STRIDE) m = STRIDE;              // structurally unreachable guard
    if (m == 0) { if (lane == 0) g_ucnt[b] = 0; return; }

    unsigned* it = s_it[warp];
    float*    sv = s_val[warp];
    const unsigned long long* src = g_pairs + (size_t)b * STRIDE;

    if (m <= 64) {
        unsigned v[2];
#pragma unroll
        for (int r = 0; r < 2; ++r) {
            int i = lane + 32 * r;
            if (i < m) {
                unsigned long long p = src[i];
                v[r] = ((((unsigned)(p >> 32)) & 0x7FFFu) << 16) | (unsigned)i;
                sv[i] = __uint_as_float((unsigned)p);
            } else v[r] = 0xFFFFFFFFu;
        }
        bitonic_reg<2>(v, lane);
#pragma unroll
        for (int r = 0; r < 2; ++r) it[lane + 32 * r] = v[r];
    } else {
        unsigned v[4];
#pragma unroll
        for (int r = 0; r < 4; ++r) {
            int i = lane + 32 * r;
            if (i < m) {
                unsigned long long p = src[i];
                v[r] = ((((unsigned)(p >> 32)) & 0x7FFFu) << 16) | (unsigned)i;
                sv[i] = __uint_as_float((unsigned)p);
            } else v[r] = 0xFFFFFFFFu;
        }
        bitonic_reg<4>(v, lane);
#pragma unroll
        for (int r = 0; r < 4; ++r) it[lane + 32 * r] = v[r];
    }
    __syncwarp();

    // Dedupe: heads sum their run (runs ~1-2), positions via ballot prefix.
    unsigned long long* dst = g_dedup + (size_t)b * STRIDE;
    unsigned kb = (unsigned)b << BSHIFT;
    int off = 0;
    for (int base = 0; base < m; base += 32) {
        int i = base + lane;
        bool head = false;
        unsigned k15 = 0;
        if (i < m) {
            k15 = it[i] >> 16;
            head = (i == 0) || ((it[i - 1] >> 16) != k15);
        }
        unsigned mask = __ballot_sync(0xFFFFFFFFu, head);
        if (head) {
            float acc = sv[it[i] & 0xFFFFu];
            int j = i + 1;
            while (j < m && (it[j] >> 16) == k15) { acc += sv[it[j] & 0xFFFFu]; ++j; }
            int pos = off + __popc(mask & ((1u << lane) - 1u));
            unsigned key = kb | k15;
            dst[pos] = ((unsigned long long)key << 32) |
                       (unsigned long long)__float_as_uint(acc);
        }
        off += __popc(mask);
    }
    if (lane == 0) g_ucnt[b] = off;
}

// ---------------------------------------------------------------------------
// Single-block scan of g_ucnt[0..NBP) -> g_uoff (exclusive), publishes total.
// int4 vectorized; padding region of g_ucnt is permanently zero.
__global__ void __launch_bounds__(SCT) scan_kernel(float* __restrict__ out, int E2o)
{
    typedef cub::BlockScan<int, SCT> BS;
    __shared__ typename BS::TempStorage ts;
    int t = threadIdx.x;
    const int4* u4 = reinterpret_cast<const int4*>(g_ucnt);
    int4*       o4 = reinterpret_cast<int4*>(g_uoff);
    int base4 = t * (SCI / 4);

    int sum = 0;
#pragma unroll
    for (int j = 0; j < SCI / 4; ++j) {
        int4 v = u4[base4 + j];
        sum += v.x + v.y + v.z + v.w;
    }
    int excl, total;
    BS(ts).ExclusiveSum(sum, excl, total);
    int run = excl;
#pragma unroll
    for (int j = 0; j < SCI / 4; ++j) {
        int4 v = u4[base4 + j];
        int4 w;
        w.x = run; run += v.x;
        w.y = run; run += v.y;
        w.z = run; run += v.z;
        w.w = run; run += v.w;
        o4[base4 + j] = w;
    }
    if (t == 0) { g_total = total; out[3 * E2o] = (float)total; }
}

// ---------------------------------------------------------------------------
// Fused final write + tail padding.
//  Blocks [0, BUCKET_BLOCKS): one warp per bucket, emit row/col/attr at
//    globally-sorted positions (< num_edges).
//  Blocks [BUCKET_BLOCKS, ...): pad positions >= num_edges with -1/-1/0 via
//    float4 (scalar fix-up for the <=3 straddle elements). No overlap.
__global__ void __launch_bounds__(256) final_pad_kernel(float* __restrict__ out, int E2o)
{
    if ((int)blockIdx.x < BUCKET_BLOCKS) {
        int warp = threadIdx.x >> 5;
        int lane = threadIdx.x & 31;
        int b = blockIdx.x * 8 + warp;
        if (b >= NB) return;
        int u = g_ucnt[b];
        if (u == 0) return;
        const unsigned long long* src = g_dedup + (size_t)b * STRIDE;
        int ob = g_uoff[b];
        for (int j = lane; j < u; j += 32) {
            unsigned long long v = src[j];
            int key = (int)(v >> 32);
            int p = ob + j;
            out[p]           = (float)(key / NNODES);
            out[E2o + p]     = (float)(key % NNODES);
            out[2 * E2o + p] = __uint_as_float((unsigned)v);
        }
    } else {
        int U  = g_total;
        int q4 = E2o >> 2;                 // E2o divisible by 4
        int U4 = (U + 3) >> 2;             // first fully-padded float4
        int i  = (blockIdx.x - BUCKET_BLOCKS) * 256 + threadIdx.x;
        if (i == 0) {                      // scalar straddle [U, 4*U4)
            int hi = 4 * U4; if (hi > E2o) hi = E2o;
            for (int j = U; j < hi; ++j) {
                out[j] = -1.0f; out[E2o + j] = -1.0f; out[2 * E2o + j] = 0.0f;
            }
        }
        int f = U4 + i;
        if (f < q4) {
            float4* o4 = reinterpret_cast<float4*>(out);
            float4 neg  = make_float4(-1.f, -1.f, -1.f, -1.f);
            float4 zero = make_float4(0.f, 0.f, 0.f, 0.f);
            o4[f]          = neg;
            o4[q4 + f]     = neg;
            o4[2 * q4 + f] = zero;
        }
    }
}

// ---------------------------------------------------------------------------
extern "C" void kernel_launch(void* const* d_in, const int* in_sizes, int n_in,
                              void* d_out, int out_size)
{
    const int*   ei  = (const int*)d_in[0];    // edge_index [2, E] int32
    const float* ea  = (const float*)d_in[1];  // edge_attr [E] float32
    const float* t   = (const float*)d_in[2];  // threshold [1]
    float*       out = (float*)d_out;

    int E   = in_sizes[1];
    int E2o = (out_size - 1) / 3;

    const int TB = 256;
    int pad_blocks = (E2o / 4 + TB - 1) / TB;  // worst case U=0

    zero_cnt_kernel<<<(NB + TB - 1) / TB, TB>>>();
    scatter_kernel<<<(E + TB - 1) / TB, TB>>>(ei, ea, t, E);
    sort_dedupe_kernel<<<(NB + 7) / 8, 256>>>();
    scan_kernel<<<1, SCT>>>(out, E2o);
    final_pad_kernel<<<BUCKET_BLOCKS + pad_blocks, TB>>>(out, E2o);
}

// round 10
// speedup vs baseline: 1.1451x; 1.1451x over previous
#include <cuda_runtime.h>
#include <cstdint>
#include <cub/cub.cuh>

// Fixed problem shape; all scratch static (device allocation forbidden).
static constexpr int NNODES = 40000;
static constexpr int SENT   = 1600000000;                 // 40000^2 < 2^31
static constexpr int BSHIFT = 15;                         // bucket = key >> 15
static constexpr int NB     = ((SENT - 1) >> BSHIFT) + 1; // 48829 buckets
static constexpr int STRIDE = 128;                        // slots/bucket (mean ~52)
static constexpr int BUCKET_BLOCKS = (NB + 7) / 8;        // 8 warps/block

// g_cnt: zero-initialized at module load; every kernel_launch leaves it zeroed
// (final_pad_kernel re-zeros it after sort_dedupe consumed it), so no upfront
// zeroing launch is needed and replays stay deterministic.
__device__ int                g_cnt[NB];
__device__ int                g_ucnt[NB];
__device__ int                g_uoff[NB];
__device__ unsigned long long g_pairs[(size_t)NB * STRIDE]; // (key<<32)|valbits
__device__ unsigned long long g_dedup[(size_t)NB * STRIDE]; // deduped pairs
__device__ unsigned char      g_temp[4u * 1024u * 1024u];   // CUB scan temp

// ---------------------------------------------------------------------------
// Scatter valid (key,val) pairs (both orientations) into fixed-stride buckets.
__global__ void scatter_kernel(const int* __restrict__ ei, const float* __restrict__ ea,
                               const float* __restrict__ t, int E)
{
    int e = blockIdx.x * blockDim.x + threadIdx.x;
    if (e >= E) return;
    float a = ea[e];
    if (a > t[0]) return;
    int r = ei[e];
    int c = ei[E + e];
    unsigned k1 = (unsigned)(r * NNODES + c);
    unsigned k2 = (unsigned)(c * NNODES + r);
    unsigned long long ab = (unsigned long long)__float_as_uint(a);
    int b1 = (int)(k1 >> BSHIFT);
    int p1 = atomicAdd(&g_cnt[b1], 1);
    if (p1 < STRIDE) g_pairs[(size_t)b1 * STRIDE + p1] = ((unsigned long long)k1 << 32) | ab;
    int b2 = (int)(k2 >> BSHIFT);
    int p2 = atomicAdd(&g_cnt[b2], 1);
    if (p2 < STRIDE) g_pairs[(size_t)b2 * STRIDE + p2] = ((unsigned long long)k2 << 32) | ab;
}

// ---------------------------------------------------------------------------
// Register-resident warp bitonic sort of P=32*R elements; element index
// i = lane + 32*r. In-lane stages (stride>=32) exchange registers; cross-lane
// stages use shfl_xor. Ascending; padding 0xFFFFFFFF sorts last.
template <int R>
__device__ __forceinline__ void bitonic_reg(unsigned v[R], int lane)
{
#pragma unroll
    for (int k = 2; k <= 32 * R; k <<= 1) {
#pragma unroll
        for (int j = k >> 1; j >= 32; j >>= 1) {
            int d = j >> 5;
#pragma unroll
            for (int r = 0; r < R; ++r) {
                if ((r & d) == 0) {
                    int i = lane + 32 * r;
                    bool up = ((i & k) == 0);
                    unsigned a = v[r], b = v[r + d];
                    if ((a > b) == up) { v[r] = b; v[r + d] = a; }
                }
            }
        }
#pragma unroll
        for (int j = ((k >> 1) > 16 ? 16 : (k >> 1)); j >= 1; j >>= 1) {
#pragma unroll
            for (int r = 0; r < R; ++r) {
                unsigned o = __shfl_xor_sync(0xFFFFFFFFu, v[r], j);
                int i = lane + 32 * r;
                bool keep_min = (((i & k) == 0) == ((lane & j) == 0));
                unsigned mn = v[r] < o ? v[r] : o;
                unsigned mx = v[r] < o ? o : v[r];
                v[r] = keep_min ? mn : mx;
            }
        }
    }
}

// One WARP per bucket (8 warps/block): register bitonic of (key15<<16|slot),
// spill once to smem, ballot dedupe with run sums, write deduped pairs + count.
__global__ void __launch_bounds__(256) sort_dedupe_kernel()
{
    __shared__ unsigned s_it[8][STRIDE];
    __shared__ float    s_val[8][STRIDE];
    int warp = threadIdx.x >> 5;
    int lane = threadIdx.x & 31;
    int b = blockIdx.x * 8 + warp;
    if (b >= NB) return;

    int m = g_cnt[b];
    if (m > STRIDE) m = STRIDE;              // structurally unreachable guard
    if (m == 0) { if (lane == 0) g_ucnt[b] = 0; return; }

    unsigned* it = s_it[warp];
    float*    sv = s_val[warp];
    const unsigned long long* src = g_pairs + (size_t)b * STRIDE;

    if (m <= 64) {
        unsigned v[2];
#pragma unroll
        for (int r = 0; r < 2; ++r) {
            int i = lane + 32 * r;
            if (i < m) {
                unsigned long long p = src[i];
                v[r] = ((((unsigned)(p >> 32)) & 0x7FFFu) << 16) | (unsigned)i;
                sv[i] = __uint_as_float((unsigned)p);
            } else v[r] = 0xFFFFFFFFu;
        }
        bitonic_reg<2>(v, lane);
#pragma unroll
        for (int r = 0; r < 2; ++r) it[lane + 32 * r] = v[r];
    } else {
        unsigned v[4];
#pragma unroll
        for (int r = 0; r < 4; ++r) {
            int i = lane + 32 * r;
            if (i < m) {
                unsigned long long p = src[i];
                v[r] = ((((unsigned)(p >> 32)) & 0x7FFFu) << 16) | (unsigned)i;
                sv[i] = __uint_as_float((unsigned)p);
            } else v[r] = 0xFFFFFFFFu;
        }
        bitonic_reg<4>(v, lane);
#pragma unroll
        for (int r = 0; r < 4; ++r) it[lane + 32 * r] = v[r];
    }
    __syncwarp();

    // Dedupe: heads sum their run (runs ~1-2), positions via ballot prefix.
    unsigned long long* dst = g_dedup + (size_t)b * STRIDE;
    unsigned kb = (unsigned)b << BSHIFT;
    int off = 0;
    for (int base = 0; base < m; base += 32) {
        int i = base + lane;
        bool head = false;
        unsigned k15 = 0;
        if (i < m) {
            k15 = it[i] >> 16;
            head = (i == 0) || ((it[i - 1] >> 16) != k15);
        }
        unsigned mask = __ballot_sync(0xFFFFFFFFu, head);
        if (head) {
            float acc = sv[it[i] & 0xFFFFu];
            int j = i + 1;
            while (j < m && (it[j] >> 16) == k15) { acc += sv[it[j] & 0xFFFFu]; ++j; }
            int pos = off + __popc(mask & ((1u << lane) - 1u));
            unsigned key = kb | k15;
            dst[pos] = ((unsigned long long)key << 32) |
                       (unsigned long long)__float_as_uint(acc);
        }
        off += __popc(mask);
    }
    if (lane == 0) g_ucnt[b] = off;
}

// ---------------------------------------------------------------------------
// Fused final write + tail padding + counter re-zero.
//  Role A, blocks [0, BUCKET_BLOCKS): one warp per bucket, emit row/col/attr
//    at globally-sorted positions; bucket NB-1 also writes num_edges.
//  Role B, next pad_blocks: pad positions >= num_edges with -1/-1/0 (float4;
//    scalar fix-up for the <=3 straddle elements).
//  Role C, remaining blocks: zero g_cnt for the next launch (self-restoring
//    invariant; g_cnt starts zeroed at module load).
__global__ void __launch_bounds__(256) final_pad_kernel(float* __restrict__ out,
                                                        int E2o, int pad_blocks)
{
    int bid = (int)blockIdx.x;
    if (bid < BUCKET_BLOCKS) {
        int warp = threadIdx.x >> 5;
        int lane = threadIdx.x & 31;
        int b = bid * 8 + warp;
        if (b >= NB) return;
        int u = g_ucnt[b];
        if (b == NB - 1 && lane == 0)
            out[3 * E2o] = (float)(g_uoff[b] + u);   // num_edges
        if (u == 0) return;
        const unsigned long long* src = g_dedup + (size_t)b * STRIDE;
        int ob = g_uoff[b];
        for (int j = lane; j < u; j += 32) {
            unsigned long long v = src[j];
            int key = (int)(v >> 32);
            int p = ob + j;
            out[p]           = (float)(key / NNODES);
            out[E2o + p]     = (float)(key % NNODES);
            out[2 * E2o + p] = __uint_as_float((unsigned)v);
        }
    } else if (bid < BUCKET_BLOCKS + pad_blocks) {
        int U  = g_uoff[NB - 1] + g_ucnt[NB - 1];
        int q4 = E2o >> 2;                 // E2o divisible by 4
        int U4 = (U + 3) >> 2;             // first fully-padded float4
        int i  = (bid - BUCKET_BLOCKS) * 256 + threadIdx.x;
        if (i == 0) {                      // scalar straddle [U, 4*U4)
            int hi = 4 * U4; if (hi > E2o) hi = E2o;
            for (int j = U; j < hi; ++j) {
                out[j] = -1.0f; out[E2o + j] = -1.0f; out[2 * E2o + j] = 0.0f;
            }
        }
        int f = U4 + i;
        if (f < q4) {
            float4* o4 = reinterpret_cast<float4*>(out);
            float4 neg  = make_float4(-1.f, -1.f, -1.f, -1.f);
            float4 zero = make_float4(0.f, 0.f, 0.f, 0.f);
            o4[f]          = neg;
            o4[q4 + f]     = neg;
            o4[2 * q4 + f] = zero;
        }
    } else {
        int i = (bid - BUCKET_BLOCKS - pad_blocks) * 256 + threadIdx.x;
        if (i < NB) g_cnt[i] = 0;          // restore invariant for next launch
    }
}

// ---------------------------------------------------------------------------
extern "C" void kernel_launch(void* const* d_in, const int* in_sizes, int n_in,
                              void* d_out, int out_size)
{
    const int*   ei  = (const int*)d_in[0];    // edge_index [2, E] int32
    const float* ea  = (const float*)d_in[1];  // edge_attr [E] float32
    const float* t   = (const float*)d_in[2];  // threshold [1]
    float*       out = (float*)d_out;

    int E   = in_sizes[1];
    int E2o = (out_size - 1) / 3;

    int *ucnt, *uoff;
    void* temp;
    cudaGetSymbolAddress((void**)&ucnt, g_ucnt);
    cudaGetSymbolAddress((void**)&uoff, g_uoff);
    cudaGetSymbolAddress(&temp,         g_temp);

    const int TB = 256;
    int pad_blocks  = (E2o / 4 + TB - 1) / TB;   // worst case U=0
    int zero_blocks = (NB + TB - 1) / TB;

    scatter_kernel<<<(E + TB - 1) / TB, TB>>>(ei, ea, t, E);
    sort_dedupe_kernel<<<(NB + 7) / 8, 256>>>();

    size_t scan_bytes = 0;
    cub::DeviceScan::ExclusiveSum(nullptr, scan_bytes, ucnt, uoff, NB);
    cub::DeviceScan::ExclusiveSum(temp, scan_bytes, ucnt, uoff, NB);

    final_pad_kernel<<<BUCKET_BLOCKS + pad_blocks + zero_blocks, TB>>>(out, E2o, pad_blocks);
}